// round 15
// baseline (speedup 1.0000x reference)
#include <cuda_runtime.h>
#include <cuda_fp16.h>
#include <math.h>
#include <stdint.h>

// Problem dims (fixed by the dataset)
#define BDIM 4096
#define CDIM 1000
#define DDIM 2048
#define NDIM (BDIM + CDIM)   // 5096 supports
#define NT1 36               // triangle tiles for W@W^T (8x8, r<=c)
#define NT2 256              // tiles for z@W^T (32x8)
#define GAP_TH 0.02f         // refine argmax when top-2 gap below this

// ---------------- scratch (device globals; no allocs allowed) ----------------
__device__ float  g_L[NDIM * CDIM];     // all logits
__device__ int    g_yhat[NDIM];
__device__ float  g_rnorm[NDIM];
__device__ int    g_cnt[CDIM];          // per-class member count
__device__ int    g_off[CDIM];          // exclusive scan of counts
__device__ int    g_pos[CDIM];          // scatter cursor
__device__ int    g_gidx[NDIM];         // class-grouped support indices
__device__ __half g_zh[BDIM * DDIM];
__device__ __half g_Wh[CDIM * DDIM];
__device__ __half g_Ph[CDIM * DDIM];    // prototype (weights^T) fp16

// ================= helpers =================
__device__ __forceinline__ uint32_t smem_u32(const void* p) {
    uint32_t a;
    asm("{ .reg .u64 t; cvta.to.shared.u64 t, %1; cvt.u32.u64 %0, t; }" : "=r"(a) : "l"(p));
    return a;
}

__device__ __forceinline__ void cp16(uint32_t dst, const void* src, bool v) {
    int n = v ? 16 : 0;
    asm volatile("cp.async.cg.shared.global [%0], [%1], 16, %2;"
                 :: "r"(dst), "l"(src), "r"(n) : "memory");
}

#define LDSM4(r, addr) \
    asm volatile("ldmatrix.sync.aligned.m8n8.x4.shared.b16 {%0,%1,%2,%3}, [%4];" \
        : "=r"((r)[0]), "=r"((r)[1]), "=r"((r)[2]), "=r"((r)[3]) : "r"(addr))

#define MMA_F16(acc, a, b) \
    asm volatile("mma.sync.aligned.m16n8k16.row.col.f32.f16.f16.f32 " \
        "{%0,%1,%2,%3}, {%4,%5,%6,%7}, {%8,%9}, {%0,%1,%2,%3};" \
        : "+f"((acc)[0]), "+f"((acc)[1]), "+f"((acc)[2]), "+f"((acc)[3]) \
        : "r"((a)[0]), "r"((a)[1]), "r"((a)[2]), "r"((a)[3]), \
          "r"((b)[0]), "r"((b)[1]))

__device__ __forceinline__ uint32_t swz(int row, int colbytes) {
    return (uint32_t)(row * 128 + (colbytes ^ ((row & 7) << 4)));
}

// ============ fused fp32->fp16 convert + row inverse-norm ============
__global__ __launch_bounds__(256) void conv_rnorm(const float* __restrict__ W,
                                                  const float* __restrict__ z,
                                                  __half* __restrict__ Wh,
                                                  __half* __restrict__ zh) {
    int j = blockIdx.x;
    const float4* src;
    __half2* dst;
    if (j < CDIM) {
        src = (const float4*)(W + (size_t)j * DDIM);
        dst = (__half2*)(Wh + (size_t)j * DDIM);
    } else {
        src = (const float4*)(z + (size_t)(j - CDIM) * DDIM);
        dst = (__half2*)(zh + (size_t)(j - CDIM) * DDIM);
    }
    int tid = threadIdx.x;
    float ss = 0.f;
#pragma unroll
    for (int u = 0; u < 2; u++) {
        int i = tid + u * 256;
        float4 v = src[i];
        dst[i * 2 + 0] = __float22half2_rn(make_float2(v.x, v.y));
        dst[i * 2 + 1] = __float22half2_rn(make_float2(v.z, v.w));
        ss += v.x * v.x + v.y * v.y + v.z * v.z + v.w * v.w;
    }
#pragma unroll
    for (int o = 16; o > 0; o >>= 1) ss += __shfl_xor_sync(0xffffffffu, ss, o);
    __shared__ float wsum[8];
    if ((tid & 31) == 0) wsum[tid >> 5] = ss;
    __syncthreads();
    if (tid == 0) {
        float t = 0.f;
#pragma unroll
        for (int w = 0; w < 8; w++) t += wsum[w];
        g_rnorm[j] = 1.f / fmaxf(sqrtf(t), 1e-12f);
    }
}

// ================= fp16 GEMM mainloop (128x128 tile, K=2048) =================
#define KT 64
#define NKT (DDIM / KT)         // 32
#define TILE_B 16384
#define STG_B (2 * TILE_B)
#define NSTAGE 3
#define SMEM_SZ (NSTAGE * STG_B)  // 98304

__device__ __forceinline__ void gemm_mainloop(
    const __half* __restrict__ A, int arow0, int alim,
    const __half* __restrict__ B, int brow0, int blim,
    char* smem, uint32_t sb, int tid, float acc[4][4][4])
{
    int lane = tid & 31, wid = tid >> 5;
    int wm = (wid >> 2) * 64, wn = (wid & 3) * 32;

#pragma unroll
    for (int mf = 0; mf < 4; mf++)
#pragma unroll
        for (int nf = 0; nf < 4; nf++)
#pragma unroll
            for (int q = 0; q < 4; q++) acc[mf][nf][q] = 0.f;

    int crow[4], ccol[4]; uint32_t cdst[4];
#pragma unroll
    for (int it = 0; it < 4; it++) {
        int c = tid + it * 256;
        crow[it] = c >> 3; ccol[it] = c & 7;
        cdst[it] = swz(crow[it], ccol[it] * 16);
    }

#define PREFETCH(kt, s) do { \
    uint32_t st = sb + (uint32_t)(s) * STG_B; \
    int k0 = (kt) * KT; \
    _Pragma("unroll") \
    for (int it = 0; it < 4; it++) { \
        int ra = arow0 + crow[it], rb = brow0 + crow[it]; \
        cp16(st + cdst[it],          A + (size_t)ra * DDIM + k0 + ccol[it] * 8, ra < alim); \
        cp16(st + TILE_B + cdst[it], B + (size_t)rb * DDIM + k0 + ccol[it] * 8, rb < blim); \
    } \
    asm volatile("cp.async.commit_group;"); \
} while (0)

    PREFETCH(0, 0);
    PREFETCH(1, 1);

    int lr = lane & 15, kadd = (lane >> 4) * 8;

    for (int kt = 0; kt < NKT; kt++) {
        if (kt < NKT - 2) asm volatile("cp.async.wait_group 1;");
        else              asm volatile("cp.async.wait_group 0;");
        __syncthreads();

        if (kt + 2 < NKT) PREFETCH(kt + 2, (kt + 2) % NSTAGE);

        uint32_t st = sb + (uint32_t)(kt % NSTAGE) * STG_B;
        uint32_t sA = st, sB = st + TILE_B;

#pragma unroll
        for (int ks = 0; ks < 4; ks++) {
            int kc = (ks * 16 + kadd) * 2;
            uint32_t a[4][4];
#pragma unroll
            for (int mf = 0; mf < 4; mf++)
                LDSM4(a[mf], sA + swz(wm + mf * 16 + lr, kc));
            uint32_t b[4][2];
#pragma unroll
            for (int nb = 0; nb < 2; nb++) {
                uint32_t t[4];
                LDSM4(t, sB + swz(wn + nb * 16 + lr, kc));
                b[nb * 2][0] = t[0]; b[nb * 2 + 1][0] = t[1];
                b[nb * 2][1] = t[2]; b[nb * 2 + 1][1] = t[3];
            }
#pragma unroll
            for (int mf = 0; mf < 4; mf++)
#pragma unroll
                for (int nf = 0; nf < 4; nf++)
                    MMA_F16(acc[mf][nf], a[mf], b[nf]);
        }
    }
#undef PREFETCH
}

// ================= merged logits GEMM (W@W^T triangle + z@W^T) =================
__global__ __launch_bounds__(256, 2)
void gemm_logits(const __half* __restrict__ Wh, const __half* __restrict__ zh,
                 float* __restrict__ L) {
    extern __shared__ char smem[];
    uint32_t sb = smem_u32(smem);
    int tid = threadIdx.x, lane = tid & 31, wid = tid >> 5;
    int wm = (wid >> 2) * 64, wn = (wid & 3) * 32;
    int bid = blockIdx.x;
    float acc[4][4][4];

    int cr = lane >> 2, cc = (lane & 3) * 2;

    if (bid < NT1) {
        int r = 0, id = bid;
        while (id >= 8 - r) { id -= 8 - r; r++; }
        int c = r + id;
        gemm_mainloop(Wh, r * 128, CDIM, Wh, c * 128, CDIM, smem, sb, tid, acc);

#pragma unroll
        for (int mf = 0; mf < 4; mf++) {
#pragma unroll
            for (int nf = 0; nf < 4; nf++) {
                int col = c * 128 + wn + nf * 8 + cc;
                if (col >= CDIM) continue;
#pragma unroll
                for (int h = 0; h < 2; h++) {
                    int row = r * 128 + wm + mf * 16 + cr + h * 8;
                    if (row >= CDIM) continue;
                    float v0 = acc[mf][nf][h * 2 + 0], v1 = acc[mf][nf][h * 2 + 1];
                    *(float2*)(L + (size_t)row * CDIM + col) = make_float2(v0, v1);
                    if (r != c) {
                        L[(size_t)col * CDIM + row] = v0;
                        L[(size_t)(col + 1) * CDIM + row] = v1;
                    }
                }
            }
        }
    } else {
        int id2 = bid - NT1;
        int bm = (id2 >> 3) * 128, bn = (id2 & 7) * 128;
        gemm_mainloop(zh, bm, BDIM, Wh, bn, CDIM, smem, sb, tid, acc);

#pragma unroll
        for (int mf = 0; mf < 4; mf++) {
#pragma unroll
            for (int nf = 0; nf < 4; nf++) {
                int col = bn + wn + nf * 8 + cc;
                if (col >= CDIM) continue;
#pragma unroll
                for (int h = 0; h < 2; h++) {
                    int row = CDIM + bm + wm + mf * 16 + cr + h * 8;
                    *(float2*)(L + (size_t)row * CDIM + col) =
                        make_float2(acc[mf][nf][h * 2 + 0], acc[mf][nf][h * 2 + 1]);
                }
            }
        }
    }
}

// ================= final GEMM: out = z @ weights =================
__global__ __launch_bounds__(256, 2)
void gemm_out(const __half* __restrict__ zh, const __half* __restrict__ Ph,
              float* __restrict__ C) {
    extern __shared__ char smem[];
    uint32_t sb = smem_u32(smem);
    int tid = threadIdx.x, lane = tid & 31, wid = tid >> 5;
    int wm = (wid >> 2) * 64, wn = (wid & 3) * 32;
    int bm = (blockIdx.x >> 3) * 128, bn = (blockIdx.x & 7) * 128;
    float acc[4][4][4];
    gemm_mainloop(zh, bm, BDIM, Ph, bn, CDIM, smem, sb, tid, acc);

    int cr = lane >> 2, cc = (lane & 3) * 2;
#pragma unroll
    for (int mf = 0; mf < 4; mf++)
#pragma unroll
        for (int nf = 0; nf < 4; nf++) {
            int col = bn + wn + nf * 8 + cc;
            if (col >= CDIM) continue;
#pragma unroll
            for (int h = 0; h < 2; h++) {
                int row = bm + wm + mf * 16 + cr + h * 8;
                *(float2*)(C + (size_t)row * CDIM + col) =
                    make_float2(acc[mf][nf][h * 2 + 0], acc[mf][nf][h * 2 + 1]);
            }
        }
}

// ================= zero counters =================
__global__ void zero_cnt() {
    int i = blockIdx.x * 256 + threadIdx.x;
    if (i < CDIM) { g_cnt[i] = 0; g_pos[i] = 0; }
}

// ========== argmax only (no entropy): max + second-max + exact refinement ==========
struct AM { float m1; int i1; float m2; };

__device__ __forceinline__ AM am_merge(AM a, AM b) {
    bool a_wins = (a.m1 > b.m1) || (a.m1 == b.m1 && a.i1 < b.i1);
    AM hi = a_wins ? a : b;
    AM lo = a_wins ? b : a;
    AM r;
    r.m1 = hi.m1; r.i1 = hi.i1;
    r.m2 = fmaxf(hi.m2, lo.m1);   // lo.m1 >= lo.m2
    return r;
}

__global__ __launch_bounds__(256) void row_argmax(const float* __restrict__ L,
                                                  const float* __restrict__ Wf,
                                                  const float* __restrict__ zf) {
    __shared__ float sv[8];
    __shared__ AM wstate[8];
    __shared__ int  cand[64];
    __shared__ int  ncand;
    __shared__ float bestv; __shared__ int besti;
    __shared__ AM rowst;

    int row = blockIdx.x;
    const float* l = L + (size_t)row * CDIM;
    int tid = threadIdx.x;

    AM st; st.m1 = -3.4e38f; st.i1 = 0x7fffffff; st.m2 = -3.4e38f;
    if (tid < 250) {               // 250 float4 = 1000 floats
        float4 v4 = *(const float4*)(l + tid * 4);
        float vv[4] = {v4.x, v4.y, v4.z, v4.w};
#pragma unroll
        for (int q = 0; q < 4; q++) {
            float v = vv[q];
            if (v > st.m1) { st.m2 = st.m1; st.m1 = v; st.i1 = tid * 4 + q; }
            else if (v > st.m2) st.m2 = v;
        }
    }
#pragma unroll
    for (int o = 16; o > 0; o >>= 1) {
        AM ot;
        ot.m1 = __shfl_xor_sync(0xffffffffu, st.m1, o);
        ot.i1 = __shfl_xor_sync(0xffffffffu, st.i1, o);
        ot.m2 = __shfl_xor_sync(0xffffffffu, st.m2, o);
        st = am_merge(st, ot);
    }
    if ((tid & 31) == 0) wstate[tid >> 5] = st;
    __syncthreads();
    if (tid == 0) {
        AM t = wstate[0];
#pragma unroll
        for (int w = 1; w < 8; w++) t = am_merge(t, wstate[w]);
        rowst = t;
        ncand = 0; bestv = -3.4e38f; besti = 0x7fffffff;
    }
    __syncthreads();
    AM fin = rowst;
    int am = fin.i1;

    if (fin.m1 - fin.m2 < GAP_TH) {
        // ambiguous argmax: collect candidates, refine exactly in fp32
        for (int c = tid; c < CDIM; c += 256) {
            if (l[c] > fin.m1 - GAP_TH) {
                int p = atomicAdd(&ncand, 1);
                if (p < 64) cand[p] = c;
            }
        }
        __syncthreads();
        int nc = min(ncand, 64);
        const float* arow = (row < CDIM) ? (Wf + (size_t)row * DDIM)
                                         : (zf + (size_t)(row - CDIM) * DDIM);
        for (int k = 0; k < nc; k++) {
            int c = cand[k];
            const float* brow = Wf + (size_t)c * DDIM;
            float p = 0.f;
            for (int d = tid; d < DDIM; d += 256) p = fmaf(arow[d], brow[d], p);
#pragma unroll
            for (int o = 16; o > 0; o >>= 1) p += __shfl_xor_sync(0xffffffffu, p, o);
            if ((tid & 31) == 0) sv[tid >> 5] = p;
            __syncthreads();
            if (tid == 0) {
                float v = 0.f;
#pragma unroll
                for (int w = 0; w < 8; w++) v += sv[w];
                if (v > bestv || (v == bestv && c < besti)) { bestv = v; besti = c; }
            }
            __syncthreads();
        }
        am = besti;
    }

    if (tid == 0) {
        g_yhat[row] = am;
        atomicAdd(&g_cnt[am], 1);   // class histogram, fused
    }
}

// ================= exclusive scan of class counts (single block) =================
__global__ __launch_bounds__(1024) void scan_cnt() {
    __shared__ int s[1024];
    int tid = threadIdx.x;
    s[tid] = (tid < CDIM) ? g_cnt[tid] : 0;
    __syncthreads();
    for (int o = 1; o < 1024; o <<= 1) {
        int v = (tid >= o) ? s[tid - o] : 0;
        __syncthreads();
        s[tid] += v;
        __syncthreads();
    }
    if (tid < CDIM) g_off[tid] = s[tid] - g_cnt[tid];
}

// ================= scatter supports into class-grouped order =================
__global__ __launch_bounds__(256) void scatter_grp() {
    int j = blockIdx.x * 256 + threadIdx.x;
    if (j >= NDIM) return;
    int c = g_yhat[j];
    int p = atomicAdd(&g_pos[c], 1);
    g_gidx[g_off[c] + p] = j;
}

// ========== per-class prototype; entropy computed lazily only if m > K ==========
__global__ __launch_bounds__(256) void select_accum(const float* __restrict__ W,
                                                    const float* __restrict__ z,
                                                    const float* __restrict__ L,
                                                    const int* __restrict__ filterK) {
    __shared__ uint32_t keepmask[(NDIM + 31) / 32];
    __shared__ float red[8];

    int c = blockIdx.x;
    int tid = threadIdx.x;
    int m = g_cnt[c], off = g_off[c];
    int K = *filterK;

    bool use_mask = (m > K);
    if (use_mask) {
        // RARE path: compute entropies of this class's members, then rank.
        extern __shared__ float ent_s[];   // [m] floats (dynamic)
        for (int w = tid; w < (m + 31) / 32; w += 256) keepmask[w] = 0u;
        __syncthreads();
        for (int i = 0; i < m; i++) {
            int j = g_gidx[off + i];
            const float* l = L + (size_t)j * CDIM;
            // block-wide max
            float mx = -3.4e38f;
            for (int q = tid; q < CDIM; q += 256) mx = fmaxf(mx, l[q]);
#pragma unroll
            for (int o = 16; o > 0; o >>= 1) mx = fmaxf(mx, __shfl_xor_sync(0xffffffffu, mx, o));
            if ((tid & 31) == 0) red[tid >> 5] = mx;
            __syncthreads();
            float rm = red[0];
#pragma unroll
            for (int w = 1; w < 8; w++) rm = fmaxf(rm, red[w]);
            // block-wide exp sums
            float s1 = 0.f, s2 = 0.f;
            for (int q = tid; q < CDIM; q += 256) {
                float d = l[q] - rm;
                float e = __expf(d);
                s1 += e; s2 += d * e;
            }
#pragma unroll
            for (int o = 16; o > 0; o >>= 1) {
                s1 += __shfl_xor_sync(0xffffffffu, s1, o);
                s2 += __shfl_xor_sync(0xffffffffu, s2, o);
            }
            __syncthreads();
            if ((tid & 31) == 0) red[tid >> 5] = s1;
            __syncthreads();
            float t1 = 0.f;
#pragma unroll
            for (int w = 0; w < 8; w++) t1 += red[w];
            __syncthreads();
            if ((tid & 31) == 0) red[tid >> 5] = s2;
            __syncthreads();
            float t2 = 0.f;
#pragma unroll
            for (int w = 0; w < 8; w++) t2 += red[w];
            if (tid == 0) ent_s[i] = logf(t1) - t2 / t1;
            __syncthreads();
        }
        // rank-based selection (tie-break: lower support index, matching jax.lax.top_k)
        for (int i = tid; i < m; i += 256) {
            float ei = ent_s[i]; int ji = g_gidx[off + i];
            int rank = 0;
            for (int q = 0; q < m; q++) {
                float eq = ent_s[q]; int jq = g_gidx[off + q];
                rank += (eq < ei) || (eq == ei && jq < ji);
            }
            if (rank < K) atomicOr(&keepmask[i >> 5], 1u << (i & 31));
        }
        __syncthreads();
    }

    float acc[DDIM / 256];
#pragma unroll
    for (int u = 0; u < DDIM / 256; u++) acc[u] = 0.f;

    for (int i = 0; i < m; i++) {
        if (use_mask && !(keepmask[i >> 5] & (1u << (i & 31)))) continue;
        int j = g_gidx[off + i];
        const float* srow = (j < CDIM) ? (W + (size_t)j * DDIM)
                                       : (z + (size_t)(j - CDIM) * DDIM);
        float rn = g_rnorm[j];
#pragma unroll
        for (int u = 0; u < DDIM / 256; u++)
            acc[u] = fmaf(srow[tid + u * 256], rn, acc[u]);
    }

    // column L2 norm via warp shuffles
    float ss = 0.f;
#pragma unroll
    for (int u = 0; u < DDIM / 256; u++) ss += acc[u] * acc[u];
#pragma unroll
    for (int o = 16; o > 0; o >>= 1) ss += __shfl_xor_sync(0xffffffffu, ss, o);
    __syncthreads();
    if ((tid & 31) == 0) red[tid >> 5] = ss;
    __syncthreads();
    float tot = 0.f;
#pragma unroll
    for (int w = 0; w < 8; w++) tot += red[w];
    float inv = 1.f / fmaxf(sqrtf(tot), 1e-12f);
#pragma unroll
    for (int u = 0; u < DDIM / 256; u++)
        g_Ph[(size_t)c * DDIM + tid + u * 256] = __float2half_rn(acc[u] * inv);
}

// ---------------- launch ----------------
extern "C" void kernel_launch(void* const* d_in, const int* in_sizes, int n_in,
                              void* d_out, int out_size) {
    const float* z  = (const float*)d_in[0];   // [4096, 2048]
    const float* W  = (const float*)d_in[1];   // [1000, 2048]
    const int*   fK = (const int*)d_in[2];     // scalar filter_K
    float* out = (float*)d_out;                // [4096, 1000]

    float* L;
    __half *zh, *Wh, *Ph;
    cudaGetSymbolAddress((void**)&L,  g_L);
    cudaGetSymbolAddress((void**)&zh, g_zh);
    cudaGetSymbolAddress((void**)&Wh, g_Wh);
    cudaGetSymbolAddress((void**)&Ph, g_Ph);

    cudaFuncSetAttribute(gemm_logits, cudaFuncAttributeMaxDynamicSharedMemorySize, SMEM_SZ);
    cudaFuncSetAttribute(gemm_out,    cudaFuncAttributeMaxDynamicSharedMemorySize, SMEM_SZ);
    // dynamic smem for rare entropy path (worst case: all supports in one class)
    cudaFuncSetAttribute(select_accum, cudaFuncAttributeMaxDynamicSharedMemorySize,
                         NDIM * (int)sizeof(float));

    dim3 thr(256);
    zero_cnt<<<(CDIM + 255) / 256, thr>>>();
    conv_rnorm<<<NDIM, thr>>>(W, z, Wh, zh);
    gemm_logits<<<NT1 + NT2, thr, SMEM_SZ>>>(Wh, zh, L);
    // argmax (+ exact refinement) + class histogram; NO entropy in common path
    row_argmax<<<NDIM, thr>>>(L, W, z);
    scan_cnt<<<1, 1024>>>();
    scatter_grp<<<(NDIM + 255) / 256, thr>>>();
    // prototypes; entropies computed lazily only for classes with m > K
    select_accum<<<CDIM, thr, NDIM * sizeof(float)>>>(W, z, L, fK);
    gemm_out<<<NT2, thr, SMEM_SZ>>>(zh, Ph, out);
}